// round 4
// baseline (speedup 1.0000x reference)
#include <cuda_runtime.h>
#include <math.h>

#define NN   8192
#define DIN  512
#define DD   64
#define NEGINF -9e15f

typedef unsigned long long u64;

// Packed fp32x2 helpers (sm_103a PTX-only ops).
#define FMA2(d, a, b) asm("fma.rn.f32x2 %0, %1, %2, %0;" : "+l"(d) : "l"(a), "l"(b))
#define MUL2(d, a)    asm("mul.rn.f32x2 %0, %0, %1;"     : "+l"(d) : "l"(a))
#define PACK2(d, x, y) asm("mov.b64 %0, {%1, %2};" : "=l"(d) : "f"(x), "f"(y))
#define UNPACK2(x, y, d) asm("mov.b64 {%0, %1}, %2;" : "=f"(x), "=f"(y) : "l"(d))

// Scratch for projected features (device globals: no allocation allowed).
__device__ float g_kh[NN * DD];
__device__ float g_vh[NN * DD];

// ---------------------------------------------------------------------------
// Kernel A: kh = X @ kW, vh = X @ vW   (8192x512 @ 512x64, fp32)
// grid = 128 (64 rows per CTA), block = 16x16, 4x4 register tile per thread.
// ---------------------------------------------------------------------------
__global__ void __launch_bounds__(256) proj_kernel(const float* __restrict__ inp,
                                                   const float* __restrict__ kW,
                                                   const float* __restrict__ vW) {
    __shared__ float sIn[64][36];
    __shared__ float sKW[32][65];
    __shared__ float sVW[32][65];

    const int tx = threadIdx.x, ty = threadIdx.y;
    const int tid = ty * 16 + tx;
    const int rbase = blockIdx.x * 64;

    float ak[4][4] = {};
    float av[4][4] = {};

    for (int kc = 0; kc < DIN; kc += 32) {
        __syncthreads();
        #pragma unroll
        for (int e = tid; e < 64 * 32; e += 256) {
            int r = e >> 5, c = e & 31;
            sIn[r][c] = inp[(rbase + r) * DIN + kc + c];
        }
        #pragma unroll
        for (int e = tid; e < 32 * 64; e += 256) {
            int r = e >> 6, c = e & 63;
            sKW[r][c] = kW[(kc + r) * DD + c];
            sVW[r][c] = vW[(kc + r) * DD + c];
        }
        __syncthreads();

        #pragma unroll 8
        for (int kk = 0; kk < 32; kk++) {
            float a[4], bk[4], bv[4];
            #pragma unroll
            for (int i = 0; i < 4; i++) a[i] = sIn[ty + 16 * i][kk];
            #pragma unroll
            for (int j = 0; j < 4; j++) {
                bk[j] = sKW[kk][tx + 16 * j];
                bv[j] = sVW[kk][tx + 16 * j];
            }
            #pragma unroll
            for (int i = 0; i < 4; i++)
                #pragma unroll
                for (int j = 0; j < 4; j++) {
                    ak[i][j] = fmaf(a[i], bk[j], ak[i][j]);
                    av[i][j] = fmaf(a[i], bv[j], av[i][j]);
                }
        }
    }

    #pragma unroll
    for (int i = 0; i < 4; i++)
        #pragma unroll
        for (int j = 0; j < 4; j++) {
            int r = rbase + ty + 16 * i;
            int c = tx + 16 * j;
            g_kh[r * DD + c] = ak[i][j];
            g_vh[r * DD + c] = av[i][j];
        }
}

// ---------------------------------------------------------------------------
// Kernel B: fused masked flash attention + ELU, f32x2 packed math.
// grid = 128 (BM=64 query rows per CTA), block = (16,32) = 512 threads.
// BN = 128 keys per tile, 64 tiles.
// Thread (tx,ty): S-tile rows {ty, ty+32} x cols {tx+16j, j<8};
//                 O-tile rows {ty, ty+32} x cols {tx+16j, j<4}.
// Packed along the reduction dim (k / key pairs); halves summed at the end.
//
// smem (floats):
//   khq : 64 x 66    query tile (stride 66: conflict-free b-side LDS.64)
//   skk : 128 x 66   key tile; ALIASED by Ps (64 x 130 = 8320 <= 8448) after S
//   svt : 64 x 130   vh transposed: svt[outcol][key]
//   red : 64 x 16    per-row partials; rowm/rowl/rowf : 64 each
// ---------------------------------------------------------------------------
#define F_KHQ 0
#define F_SKK (F_KHQ + 64 * 66)
#define F_PS  F_SKK
#define F_SVT (F_SKK + 128 * 66)
#define F_RED (F_SVT + 64 * 130)
#define F_RM  (F_RED + 64 * 16)
#define F_RL  (F_RM + 64)
#define F_RF  (F_RL + 64)
#define SMEM_B_BYTES ((F_RF + 64) * 4)

__global__ void __launch_bounds__(512, 1) attn_kernel(const int* __restrict__ adj,
                                                      float* __restrict__ out) {
    extern __shared__ float sm[];
    float* khq  = sm + F_KHQ;
    float* skk  = sm + F_SKK;
    float* Ps   = sm + F_PS;
    float* svt  = sm + F_SVT;
    float* red  = sm + F_RED;
    float* rowm = sm + F_RM;
    float* rowl = sm + F_RL;
    float* rowf = sm + F_RF;

    const int tx = threadIdx.x, ty = threadIdx.y;
    const int tid = ty * 16 + tx;
    const int qbase = blockIdx.x * 64;

    // Query tile (once) + row-state init.
    for (int e = tid; e < 64 * 64; e += 512) {
        int r = e >> 6, c = e & 63;
        khq[r * 66 + c] = g_kh[(qbase + r) * DD + c];
    }
    if (tid < 64) { rowm[tid] = NEGINF; rowl[tid] = 0.f; }

    u64 o2[2][4];
    #pragma unroll
    for (int i = 0; i < 2; i++)
        #pragma unroll
        for (int j = 0; j < 4; j++) o2[i][j] = 0ULL;

    for (int t = 0; t < NN / 128; t++) {
        const int kbase = t * 128;
        __syncthreads();                                   // S1

        // Fill key tile (float2, coalesced).
        for (int e = tid; e < 128 * 32; e += 512) {
            int r = e >> 5, q = e & 31;
            *(float2*)&skk[r * 66 + 2 * q] =
                *(const float2*)&g_kh[(kbase + r) * DD + 2 * q];
        }
        // Fill transposed value tile: svt[c][key] = vh[kbase+key][c].
        for (int e = tid; e < 128 * 64; e += 512) {
            int key = e >> 6, c = e & 63;
            svt[c * 130 + key] = g_vh[(kbase + key) * DD + c];
        }

        // adj -> bitmasks (2 rows x 8 cols per thread).
        unsigned msk[2];
        #pragma unroll
        for (int i = 0; i < 2; i++) {
            msk[i] = 0u;
            const int* arow = adj + (long)(qbase + ty + 32 * i) * NN + kbase;
            #pragma unroll
            for (int j = 0; j < 8; j++)
                if (arow[tx + 16 * j] > 0) msk[i] |= (1u << j);
        }
        __syncthreads();                                   // S2

        // S = khq @ skk^T, packed along k (32 k-pairs).
        u64 s2[2][8];
        #pragma unroll
        for (int i = 0; i < 2; i++)
            #pragma unroll
            for (int j = 0; j < 8; j++) s2[i][j] = 0ULL;

        #pragma unroll 8
        for (int kp = 0; kp < 32; kp++) {
            u64 a2[2], b2[8];
            #pragma unroll
            for (int i = 0; i < 2; i++)
                a2[i] = *(const u64*)&khq[(ty + 32 * i) * 66 + 2 * kp];
            #pragma unroll
            for (int j = 0; j < 8; j++)
                b2[j] = *(const u64*)&skk[(tx + 16 * j) * 66 + 2 * kp];
            #pragma unroll
            for (int i = 0; i < 2; i++)
                #pragma unroll
                for (int j = 0; j < 8; j++)
                    FMA2(s2[i][j], a2[i], b2[j]);
        }

        // Unpack, mask + scale, partial row max.
        float s[2][8];
        #pragma unroll
        for (int i = 0; i < 2; i++) {
            float pm = NEGINF;
            #pragma unroll
            for (int j = 0; j < 8; j++) {
                float lo, hi;
                UNPACK2(lo, hi, s2[i][j]);
                s[i][j] = ((msk[i] >> j) & 1u) ? (lo + hi) * 0.125f : NEGINF;
                pm = fmaxf(pm, s[i][j]);
            }
            red[(ty + 32 * i) * 16 + tx] = pm;
        }
        __syncthreads();                                   // S3

        // Row max + rescale factor (one thread per row).
        if (tid < 64) {
            float mm = NEGINF;
            #pragma unroll
            for (int x = 0; x < 16; x++) mm = fmaxf(mm, red[tid * 16 + x]);
            float mo = rowm[tid];
            float mn = fmaxf(mo, mm);
            rowf[tid] = __expf(mo - mn);
            rowm[tid] = mn;
        }
        __syncthreads();                                   // S4

        // p = exp(s - m); stage Ps (stride 130, full 128 cols); rescale o2.
        #pragma unroll
        for (int i = 0; i < 2; i++) {
            int row = ty + 32 * i;
            float mn = rowm[row];
            float f  = rowf[row];
            float ps = 0.f;
            #pragma unroll
            for (int j = 0; j < 8; j++) {
                float p = __expf(s[i][j] - mn);
                Ps[row * 130 + tx + 16 * j] = p;
                ps += p;
            }
            red[row * 16 + tx] = ps;
            u64 ff;
            PACK2(ff, f, f);
            #pragma unroll
            for (int j = 0; j < 4; j++) MUL2(o2[i][j], ff);
        }
        __syncthreads();                                   // S5

        // Denominator update (one thread per row).
        if (tid < 64) {
            float rs = 0.f;
            #pragma unroll
            for (int x = 0; x < 16; x++) rs += red[tid * 16 + x];
            rowl[tid] = rowl[tid] * rowf[tid] + rs;
        }

        // O += P @ vh, packed along key (64 key-pairs).
        #pragma unroll 8
        for (int cp = 0; cp < 64; cp++) {
            u64 p2[2], v2[4];
            #pragma unroll
            for (int i = 0; i < 2; i++)
                p2[i] = *(const u64*)&Ps[(ty + 32 * i) * 130 + 2 * cp];
            #pragma unroll
            for (int j = 0; j < 4; j++)
                v2[j] = *(const u64*)&svt[(tx + 16 * j) * 130 + 2 * cp];
            #pragma unroll
            for (int i = 0; i < 2; i++)
                #pragma unroll
                for (int j = 0; j < 4; j++)
                    FMA2(o2[i][j], p2[i], v2[j]);
        }
    }

    __syncthreads();   // final rowl visible

    // Sum packed halves, normalize, ELU, store.
    #pragma unroll
    for (int i = 0; i < 2; i++) {
        int row = ty + 32 * i;
        float inv = 1.f / rowl[row];
        #pragma unroll
        for (int j = 0; j < 4; j++) {
            float lo, hi;
            UNPACK2(lo, hi, o2[i][j]);
            float x = (lo + hi) * inv;
            x = (x > 0.f) ? x : expm1f(x);
            out[(qbase + row) * DD + tx + 16 * j] = x;
        }
    }
}

namespace {
struct AttrInit {
    AttrInit() {
        cudaFuncSetAttribute(attn_kernel,
                             cudaFuncAttributeMaxDynamicSharedMemorySize,
                             SMEM_B_BYTES);
    }
} attr_init_;
}

extern "C" void kernel_launch(void* const* d_in, const int* in_sizes, int n_in,
                              void* d_out, int out_size) {
    // Bind inputs by SIZE (robust to metadata ordering).
    const float* inp = nullptr;
    const int*   adj = nullptr;
    const float* kW  = nullptr;
    const float* vW  = nullptr;
    for (int i = 0; i < n_in; i++) {
        long sz = in_sizes[i];
        if (sz == (long)NN * DIN)      inp = (const float*)d_in[i];
        else if (sz == (long)NN * NN)  adj = (const int*)d_in[i];
        else if (sz == (long)DIN * DD) { if (!kW) kW = (const float*)d_in[i];
                                         else     vW = (const float*)d_in[i]; }
    }
    float* out = (float*)d_out;

    cudaFuncSetAttribute(attn_kernel,
                         cudaFuncAttributeMaxDynamicSharedMemorySize,
                         SMEM_B_BYTES);

    proj_kernel<<<NN / 64, dim3(16, 16)>>>(inp, kW, vW);
    attn_kernel<<<NN / 64, dim3(16, 32), SMEM_B_BYTES>>>(adj, out);
}

// round 6
// speedup vs baseline: 2.0199x; 2.0199x over previous
#include <cuda_runtime.h>
#include <cuda_bf16.h>
#include <math.h>
#include <stdint.h>

#define NN   8192
#define DIN  512
#define DD   64

// ===========================================================================
// Device globals (no allocation allowed).
// ===========================================================================
__device__ float          g_kh[NN * DD];     // fp32 kh (for norms)
__device__ __nv_bfloat16  g_khhi[NN * DD];
__device__ __nv_bfloat16  g_khlo[NN * DD];
__device__ __nv_bfloat16  g_vhhi[NN * DD];
__device__ __nv_bfloat16  g_vhlo[NN * DD];
__device__ float          g_norm[NN];
__device__ unsigned       g_maxnorm_bits;

// ===========================================================================
// Helpers
// ===========================================================================
__device__ __forceinline__ uint32_t smem_u32(const void* p) {
    uint32_t a;
    asm("{ .reg .u64 t; cvta.to.shared.u64 t, %1; cvt.u32.u64 %0, t; }"
        : "=r"(a) : "l"(p));
    return a;
}
#define SW128(x) ((uint32_t)(x) ^ ((((uint32_t)(x)) >> 3) & 0x70))

__device__ __forceinline__ void mma16816(float* d,
    uint32_t a0, uint32_t a1, uint32_t a2, uint32_t a3,
    uint32_t b0, uint32_t b1) {
    asm volatile(
        "mma.sync.aligned.m16n8k16.row.col.f32.bf16.bf16.f32 "
        "{%0,%1,%2,%3},{%4,%5,%6,%7},{%8,%9},{%0,%1,%2,%3};"
        : "+f"(d[0]), "+f"(d[1]), "+f"(d[2]), "+f"(d[3])
        : "r"(a0), "r"(a1), "r"(a2), "r"(a3), "r"(b0), "r"(b1));
}
#define LDSM4(r0, r1, r2, r3, a)                                        \
    asm volatile("ldmatrix.sync.aligned.m8n8.x4.shared.b16 "            \
                 "{%0,%1,%2,%3}, [%4];"                                 \
                 : "=r"(r0), "=r"(r1), "=r"(r2), "=r"(r3) : "r"(a))
#define LDSM4T(r0, r1, r2, r3, a)                                       \
    asm volatile("ldmatrix.sync.aligned.m8n8.x4.trans.shared.b16 "      \
                 "{%0,%1,%2,%3}, [%4];"                                 \
                 : "=r"(r0), "=r"(r1), "=r"(r2), "=r"(r3) : "r"(a))

// ===========================================================================
// Stage 1 kernels
// ===========================================================================
__global__ void init_kernel() { g_maxnorm_bits = 0u; }

__global__ void __launch_bounds__(256) proj_kernel(const float* __restrict__ inp,
                                                   const float* __restrict__ kW,
                                                   const float* __restrict__ vW) {
    __shared__ float sIn[64][36];
    __shared__ float sKW[32][65];
    __shared__ float sVW[32][65];
    const int tx = threadIdx.x, ty = threadIdx.y;
    const int tid = ty * 16 + tx;
    const int rbase = blockIdx.x * 64;
    float ak[4][4] = {}, av[4][4] = {};

    for (int kc = 0; kc < DIN; kc += 32) {
        __syncthreads();
        for (int e = tid; e < 64 * 32; e += 256) {
            int r = e >> 5, c = e & 31;
            sIn[r][c] = inp[(rbase + r) * DIN + kc + c];
        }
        for (int e = tid; e < 32 * 64; e += 256) {
            int r = e >> 6, c = e & 63;
            sKW[r][c] = kW[(kc + r) * DD + c];
            sVW[r][c] = vW[(kc + r) * DD + c];
        }
        __syncthreads();
        #pragma unroll 8
        for (int kk = 0; kk < 32; kk++) {
            float a[4], bk[4], bv[4];
            #pragma unroll
            for (int i = 0; i < 4; i++) a[i] = sIn[ty + 16 * i][kk];
            #pragma unroll
            for (int j = 0; j < 4; j++) { bk[j] = sKW[kk][tx + 16 * j];
                                          bv[j] = sVW[kk][tx + 16 * j]; }
            #pragma unroll
            for (int i = 0; i < 4; i++)
                #pragma unroll
                for (int j = 0; j < 4; j++) {
                    ak[i][j] = fmaf(a[i], bk[j], ak[i][j]);
                    av[i][j] = fmaf(a[i], bv[j], av[i][j]);
                }
        }
    }
    #pragma unroll
    for (int i = 0; i < 4; i++)
        #pragma unroll
        for (int j = 0; j < 4; j++) {
            int idx = (rbase + ty + 16 * i) * DD + tx + 16 * j;
            float kv = ak[i][j], vv = av[i][j];
            g_kh[idx] = kv;
            __nv_bfloat16 kh = __float2bfloat16(kv);
            g_khhi[idx] = kh;
            g_khlo[idx] = __float2bfloat16(kv - __bfloat162float(kh));
            __nv_bfloat16 vh = __float2bfloat16(vv);
            g_vhhi[idx] = vh;
            g_vhlo[idx] = __float2bfloat16(vv - __bfloat162float(vh));
        }
}

__global__ void __launch_bounds__(256) norm_kernel() {
    int r = blockIdx.x * 256 + threadIdx.x;
    const float4* p = (const float4*)(g_kh + r * DD);
    float s = 0.f;
    #pragma unroll
    for (int i = 0; i < 16; i++) {
        float4 v = p[i];
        s += v.x * v.x + v.y * v.y + v.z * v.z + v.w * v.w;
    }
    float n = sqrtf(s);
    g_norm[r] = n;
    atomicMax(&g_maxnorm_bits, __float_as_uint(n));
}

// ===========================================================================
// Stage 2: HMMA (mma.sync bf16) flash attention with fixed per-row max.
// grid = 128 (64 q rows / CTA), 128 threads (4 warps).
// Warp w owns S rows [w*16, w*16+16) x all 128 keys of the tile.
// smem: Khi 0..16K | Klo 16K..32K | Vhi 32K..48K | Vlo 48K..64K
//       (Q staged transiently at offsets 0 / 8K before the main loop)
// ===========================================================================
#define SM_KHI 0
#define SM_KLO 16384
#define SM_VHI 32768
#define SM_VLO 49152
#define SMEM_ATTN 65536

__global__ void __launch_bounds__(128, 1)
attn_kernel(const int* __restrict__ adj, float* __restrict__ out) {
    extern __shared__ char smem[];
    const uint32_t sb = smem_u32(smem);
    const int tid  = threadIdx.x;
    const int w    = tid >> 5;
    const int lane = tid & 31;
    const int g    = lane >> 2;          // fragment row group (0..7)
    const int tg   = lane & 3;           // fragment col group
    const int q0   = w * 16;             // warp's first CTA-local row
    const int qbase = blockIdx.x * 64;

    // ---- Stage Q (hi at SM_KHI, lo at +8192), extract A fragments, free smem
    for (int i = 0; i < 4; i++) {
        int e = i * 128 + tid;           // 512 16B units
        int r = e >> 3, b = e & 7;
        uint32_t sw = SW128(r * 128 + b * 16);
        *(uint4*)(smem + sw) =
            *(const uint4*)(g_khhi + (qbase + r) * DD + b * 8);
        *(uint4*)(smem + 8192 + sw) =
            *(const uint4*)(g_khlo + (qbase + r) * DD + b * 8);
    }
    __syncthreads();

    uint32_t qh[16], ql[16];
    {
        int arow = q0 + ((lane >> 3) & 1) * 8 + (lane & 7);
        int acol0 = (lane >> 4) * 8;
        #pragma unroll
        for (int ks = 0; ks < 4; ks++) {
            uint32_t sw = SW128(arow * 128 + (ks * 16 + acol0) * 2);
            LDSM4(qh[4*ks], qh[4*ks+1], qh[4*ks+2], qh[4*ks+3], sb + sw);
            LDSM4(ql[4*ks], ql[4*ks+1], ql[4*ks+2], ql[4*ks+3], sb + 8192 + sw);
        }
    }
    __syncthreads();

    // Fixed per-row max bounds (Cauchy-Schwarz), rows g and g+8 of this thread.
    const float maxn = __uint_as_float(g_maxnorm_bits) * 0.125f * 1.0001f;
    const float mq0 = g_norm[qbase + q0 + g] * maxn;
    const float mq1 = g_norm[qbase + q0 + g + 8] * maxn;

    float o[8][4];
    #pragma unroll
    for (int i = 0; i < 8; i++)
        #pragma unroll
        for (int j = 0; j < 4; j++) o[i][j] = 0.f;
    float l0 = 0.f, l1 = 0.f;

    // ldmatrix address components (reused every tile)
    const int krow_l = (lane >> 4) * 8 + (lane & 7);        // K (B, non-trans)
    const int kcol_l = ((lane >> 3) & 1) * 8;
    const int vrow_l = ((lane >> 3) & 1) * 8 + (lane & 7);  // V (B, trans)
    const int vcol_l = (lane >> 4) * 8;

    for (int t = 0; t < NN / 128; t++) {
        const int kbase = t * 128;
        __syncthreads();

        // ---- Fill K/V hi/lo tiles (coalesced 16B units, SW128 stores)
        #pragma unroll
        for (int i = 0; i < 8; i++) {
            int e = i * 128 + tid;       // 1024 units = 128 rows x 8
            int r = e >> 3, b = e & 7;
            uint32_t sw = SW128(r * 128 + b * 16);
            long src = (long)(kbase + r) * DD + b * 8;
            *(uint4*)(smem + SM_KHI + sw) = *(const uint4*)(g_khhi + src);
            *(uint4*)(smem + SM_KLO + sw) = *(const uint4*)(g_khlo + src);
            *(uint4*)(smem + SM_VHI + sw) = *(const uint4*)(g_vhhi + src);
            *(uint4*)(smem + SM_VLO + sw) = *(const uint4*)(g_vhlo + src);
        }

        // ---- adj bitmasks for this warp's 16 rows (ballots, kept in regs)
        uint4 mw0, mw1;
        #pragma unroll
        for (int rr = 0; rr < 16; rr++) {
            const int* arow = adj + (long)(qbase + q0 + rr) * NN + kbase;
            unsigned b0 = __ballot_sync(0xffffffffu, arow[lane] > 0);
            unsigned b1 = __ballot_sync(0xffffffffu, arow[32 + lane] > 0);
            unsigned b2 = __ballot_sync(0xffffffffu, arow[64 + lane] > 0);
            unsigned b3 = __ballot_sync(0xffffffffu, arow[96 + lane] > 0);
            if (rr == g)     mw0 = make_uint4(b0, b1, b2, b3);
            if (rr == g + 8) mw1 = make_uint4(b0, b1, b2, b3);
        }
        __syncthreads();

        // ---- S = Q K^T (3 split passes fused per fragment)
        float s[16][4];
        #pragma unroll
        for (int i = 0; i < 16; i++)
            #pragma unroll
            for (int j = 0; j < 4; j++) s[i][j] = 0.f;

        #pragma unroll
        for (int ks = 0; ks < 4; ks++) {
            #pragma unroll
            for (int np = 0; np < 8; np++) {
                uint32_t sw = SW128((np * 16 + krow_l) * 128 +
                                    (ks * 16 + kcol_l) * 2);
                uint32_t b0, b1, b2, b3;
                LDSM4(b0, b1, b2, b3, sb + SM_KHI + sw);
                mma16816(s[2*np],   qh[4*ks], qh[4*ks+1], qh[4*ks+2], qh[4*ks+3], b0, b1);
                mma16816(s[2*np+1], qh[4*ks], qh[4*ks+1], qh[4*ks+2], qh[4*ks+3], b2, b3);
                mma16816(s[2*np],   ql[4*ks], ql[4*ks+1], ql[4*ks+2], ql[4*ks+3], b0, b1);
                mma16816(s[2*np+1], ql[4*ks], ql[4*ks+1], ql[4*ks+2], ql[4*ks+3], b2, b3);
                uint32_t c0, c1, c2, c3;
                LDSM4(c0, c1, c2, c3, sb + SM_KLO + sw);
                mma16816(s[2*np],   qh[4*ks], qh[4*ks+1], qh[4*ks+2], qh[4*ks+3], c0, c1);
                mma16816(s[2*np+1], qh[4*ks], qh[4*ks+1], qh[4*ks+2], qh[4*ks+3], c2, c3);
            }
        }

        // ---- mask + exp(fixed m) + pack P hi/lo into A-fragment registers
        uint32_t phA[16], phB[16], plA[16], plB[16];
        const unsigned* w0 = (const unsigned*)&mw0;
        const unsigned* w1 = (const unsigned*)&mw1;
        #pragma unroll
        for (int nt = 0; nt < 16; nt++) {
            int bit = ((nt & 3) << 3) + 2 * tg;
            unsigned u0 = w0[nt >> 2], u1 = w1[nt >> 2];
            float p0 = ((u0 >> bit) & 1u)       ? __expf(fmaf(s[nt][0], 0.125f, -mq0)) : 0.f;
            float p1 = ((u0 >> (bit + 1)) & 1u) ? __expf(fmaf(s[nt][1], 0.125f, -mq0)) : 0.f;
            float p2 = ((u1 >> bit) & 1u)       ? __expf(fmaf(s[nt][2], 0.125f, -mq1)) : 0.f;
            float p3 = ((u1 >> (bit + 1)) & 1u) ? __expf(fmaf(s[nt][3], 0.125f, -mq1)) : 0.f;
            l0 += p0 + p1;
            l1 += p2 + p3;
            __nv_bfloat16 h0 = __float2bfloat16(p0), h1 = __float2bfloat16(p1);
            __nv_bfloat16 h2 = __float2bfloat16(p2), h3 = __float2bfloat16(p3);
            __nv_bfloat162 t0 = __halves2bfloat162(h0, h1);
            __nv_bfloat162 t1 = __halves2bfloat162(h2, h3);
            phA[nt] = *(uint32_t*)&t0;
            phB[nt] = *(uint32_t*)&t1;
            __nv_bfloat162 r0 = __floats2bfloat162_rn(p0 - __bfloat162float(h0),
                                                      p1 - __bfloat162float(h1));
            __nv_bfloat162 r1 = __floats2bfloat162_rn(p2 - __bfloat162float(h2),
                                                      p3 - __bfloat162float(h3));
            plA[nt] = *(uint32_t*)&r0;
            plB[nt] = *(uint32_t*)&r1;
        }

        // ---- O += P V (Phi*Vhi + Plo*Vhi + Phi*Vlo)
        #pragma unroll
        for (int ks = 0; ks < 8; ks++) {
            uint32_t ah0 = phA[2*ks], ah1 = phB[2*ks], ah2 = phA[2*ks+1], ah3 = phB[2*ks+1];
            uint32_t al0 = plA[2*ks], al1 = plB[2*ks], al2 = plA[2*ks+1], al3 = plB[2*ks+1];
            #pragma unroll
            for (int np = 0; np < 4; np++) {
                uint32_t sw = SW128((ks * 16 + vrow_l) * 128 +
                                    (np * 16 + vcol_l) * 2);
                uint32_t v0, v1, v2, v3;
                LDSM4T(v0, v1, v2, v3, sb + SM_VHI + sw);
                mma16816(o[2*np],   ah0, ah1, ah2, ah3, v0, v1);
                mma16816(o[2*np+1], ah0, ah1, ah2, ah3, v2, v3);
                mma16816(o[2*np],   al0, al1, al2, al3, v0, v1);
                mma16816(o[2*np+1], al0, al1, al2, al3, v2, v3);
                uint32_t u0, u1, u2, u3;
                LDSM4T(u0, u1, u2, u3, sb + SM_VLO + sw);
                mma16816(o[2*np],   ah0, ah1, ah2, ah3, u0, u1);
                mma16816(o[2*np+1], ah0, ah1, ah2, ah3, u2, u3);
            }
        }
    }

    // ---- reduce denominators across the 4-thread row group
    l0 += __shfl_xor_sync(0xffffffffu, l0, 1);
    l0 += __shfl_xor_sync(0xffffffffu, l0, 2);
    l1 += __shfl_xor_sync(0xffffffffu, l1, 1);
    l1 += __shfl_xor_sync(0xffffffffu, l1, 2);
    float inv0 = 1.f / l0, inv1 = 1.f / l1;

    // ---- normalize + ELU + store
    int gr0 = qbase + q0 + g, gr1 = gr0 + 8;
    #pragma unroll
    for (int nt = 0; nt < 8; nt++) {
        float x0 = o[nt][0] * inv0; x0 = (x0 > 0.f) ? x0 : expm1f(x0);
        float x1 = o[nt][1] * inv0; x1 = (x1 > 0.f) ? x1 : expm1f(x1);
        float x2 = o[nt][2] * inv1; x2 = (x2 > 0.f) ? x2 : expm1f(x2);
        float x3 = o[nt][3] * inv1; x3 = (x3 > 0.f) ? x3 : expm1f(x3);
        *(float2*)(out + (long)gr0 * DD + nt * 8 + 2 * tg) = make_float2(x0, x1);
        *(float2*)(out + (long)gr1 * DD + nt * 8 + 2 * tg) = make_float2(x2, x3);
    }
}

namespace {
struct AttrInit {
    AttrInit() {
        cudaFuncSetAttribute(attn_kernel,
                             cudaFuncAttributeMaxDynamicSharedMemorySize,
                             SMEM_ATTN);
    }
} attr_init_;
}

extern "C" void kernel_launch(void* const* d_in, const int* in_sizes, int n_in,
                              void* d_out, int out_size) {
    const float* inp = nullptr;
    const int*   adj = nullptr;
    const float* kW  = nullptr;
    const float* vW  = nullptr;
    for (int i = 0; i < n_in; i++) {
        long sz = in_sizes[i];
        if (sz == (long)NN * DIN)      inp = (const float*)d_in[i];
        else if (sz == (long)NN * NN)  adj = (const int*)d_in[i];
        else if (sz == (long)DIN * DD) { if (!kW) kW = (const float*)d_in[i];
                                         else     vW = (const float*)d_in[i]; }
    }
    float* out = (float*)d_out;

    cudaFuncSetAttribute(attn_kernel,
                         cudaFuncAttributeMaxDynamicSharedMemorySize, SMEM_ATTN);

    init_kernel<<<1, 1>>>();
    proj_kernel<<<NN / 64, dim3(16, 16)>>>(inp, kW, vW);
    norm_kernel<<<NN / 256, 256>>>();
    attn_kernel<<<NN / 64, 128, SMEM_ATTN>>>(adj, out);
}

// round 7
// speedup vs baseline: 3.6328x; 1.7985x over previous
#include <cuda_runtime.h>
#include <cuda_bf16.h>
#include <math.h>
#include <stdint.h>

#define NN   8192
#define DIN  512
#define DD   64

// ===========================================================================
// Device globals (no allocation allowed).
// ===========================================================================
__device__ float          g_kh[NN * DD];     // fp32 kh (for norms)
__device__ __nv_bfloat16  g_khhi[NN * DD];
__device__ __nv_bfloat16  g_khlo[NN * DD];
__device__ __nv_bfloat16  g_vhhi[NN * DD];
__device__ __nv_bfloat16  g_vhlo[NN * DD];
__device__ float          g_norm[NN];
__device__ unsigned       g_maxnorm_bits;

// ===========================================================================
// Helpers
// ===========================================================================
__device__ __forceinline__ uint32_t smem_u32(const void* p) {
    uint32_t a;
    asm("{ .reg .u64 t; cvta.to.shared.u64 t, %1; cvt.u32.u64 %0, t; }"
        : "=r"(a) : "l"(p));
    return a;
}
#define SW128(x) ((uint32_t)(x) ^ ((((uint32_t)(x)) >> 3) & 0x70))

__device__ __forceinline__ void mma16816(float* d,
    uint32_t a0, uint32_t a1, uint32_t a2, uint32_t a3,
    uint32_t b0, uint32_t b1) {
    asm volatile(
        "mma.sync.aligned.m16n8k16.row.col.f32.bf16.bf16.f32 "
        "{%0,%1,%2,%3},{%4,%5,%6,%7},{%8,%9},{%0,%1,%2,%3};"
        : "+f"(d[0]), "+f"(d[1]), "+f"(d[2]), "+f"(d[3])
        : "r"(a0), "r"(a1), "r"(a2), "r"(a3), "r"(b0), "r"(b1));
}
#define LDSM4(r0, r1, r2, r3, a)                                        \
    asm volatile("ldmatrix.sync.aligned.m8n8.x4.shared.b16 "            \
                 "{%0,%1,%2,%3}, [%4];"                                 \
                 : "=r"(r0), "=r"(r1), "=r"(r2), "=r"(r3) : "r"(a))
#define LDSM4T(r0, r1, r2, r3, a)                                       \
    asm volatile("ldmatrix.sync.aligned.m8n8.x4.trans.shared.b16 "      \
                 "{%0,%1,%2,%3}, [%4];"                                 \
                 : "=r"(r0), "=r"(r1), "=r"(r2), "=r"(r3) : "r"(a))
#define CP16(dst, src)                                                  \
    asm volatile("cp.async.cg.shared.global [%0], [%1], 16;"            \
                 :: "r"(dst), "l"(src))
#define CP_COMMIT() asm volatile("cp.async.commit_group;" ::: "memory")

// ===========================================================================
// Stage 1 kernels
// ===========================================================================
__global__ void init_kernel() { g_maxnorm_bits = 0u; }

__global__ void __launch_bounds__(256) proj_kernel(const float* __restrict__ inp,
                                                   const float* __restrict__ kW,
                                                   const float* __restrict__ vW) {
    __shared__ float sIn[64][36];
    __shared__ float sKW[32][65];
    __shared__ float sVW[32][65];
    const int tx = threadIdx.x, ty = threadIdx.y;
    const int tid = ty * 16 + tx;
    const int rbase = blockIdx.x * 64;
    float ak[4][4] = {}, av[4][4] = {};

    for (int kc = 0; kc < DIN; kc += 32) {
        __syncthreads();
        for (int e = tid; e < 64 * 32; e += 256) {
            int r = e >> 5, c = e & 31;
            sIn[r][c] = inp[(rbase + r) * DIN + kc + c];
        }
        for (int e = tid; e < 32 * 64; e += 256) {
            int r = e >> 6, c = e & 63;
            sKW[r][c] = kW[(kc + r) * DD + c];
            sVW[r][c] = vW[(kc + r) * DD + c];
        }
        __syncthreads();
        #pragma unroll 8
        for (int kk = 0; kk < 32; kk++) {
            float a[4], bk[4], bv[4];
            #pragma unroll
            for (int i = 0; i < 4; i++) a[i] = sIn[ty + 16 * i][kk];
            #pragma unroll
            for (int j = 0; j < 4; j++) { bk[j] = sKW[kk][tx + 16 * j];
                                          bv[j] = sVW[kk][tx + 16 * j]; }
            #pragma unroll
            for (int i = 0; i < 4; i++)
                #pragma unroll
                for (int j = 0; j < 4; j++) {
                    ak[i][j] = fmaf(a[i], bk[j], ak[i][j]);
                    av[i][j] = fmaf(a[i], bv[j], av[i][j]);
                }
        }
    }
    #pragma unroll
    for (int i = 0; i < 4; i++)
        #pragma unroll
        for (int j = 0; j < 4; j++) {
            int idx = (rbase + ty + 16 * i) * DD + tx + 16 * j;
            float kv = ak[i][j], vv = av[i][j];
            g_kh[idx] = kv;
            __nv_bfloat16 kh = __float2bfloat16(kv);
            g_khhi[idx] = kh;
            g_khlo[idx] = __float2bfloat16(kv - __bfloat162float(kh));
            __nv_bfloat16 vh = __float2bfloat16(vv);
            g_vhhi[idx] = vh;
            g_vhlo[idx] = __float2bfloat16(vv - __bfloat162float(vh));
        }
}

__global__ void __launch_bounds__(256) norm_kernel() {
    int r = blockIdx.x * 256 + threadIdx.x;
    const float4* p = (const float4*)(g_kh + r * DD);
    float s = 0.f;
    #pragma unroll
    for (int i = 0; i < 16; i++) {
        float4 v = p[i];
        s += v.x * v.x + v.y * v.y + v.z * v.z + v.w * v.w;
    }
    float n = sqrtf(s);
    g_norm[r] = n;
    atomicMax(&g_maxnorm_bits, __float_as_uint(n));
}

// ===========================================================================
// Stage 2: HMMA flash attention, fixed per-row max, 8 warps, key-split halves.
// grid = 128 (64 q rows / CTA), 256 threads.
// warp w: q-band (w&3)*16, key half (w>>2)*64 within each 128-key tile.
// smem: 2 slots x (Khi|Klo|Vhi|Vlo), 16KB each => 128KB, double buffered.
// ===========================================================================
#define SLOT_BYTES 65536
#define OFF_KHI 0
#define OFF_KLO 16384
#define OFF_VHI 32768
#define OFF_VLO 49152
#define SMEM_ATTN (2 * SLOT_BYTES)
#define TILES (NN / 128)

__device__ __forceinline__ void fill_tile(uint32_t sb, int slot, int kbase, int tid) {
    const uint32_t base = sb + slot * SLOT_BYTES;
    #pragma unroll
    for (int i = 0; i < 4; i++) {
        int e = i * 256 + tid;          // 1024 16B units per array
        int r = e >> 3, b = e & 7;
        uint32_t sw = SW128(r * 128 + b * 16);
        long src = (long)(kbase + r) * DD + b * 8;
        CP16(base + OFF_KHI + sw, g_khhi + src);
        CP16(base + OFF_KLO + sw, g_khlo + src);
        CP16(base + OFF_VHI + sw, g_vhhi + src);
        CP16(base + OFF_VLO + sw, g_vhlo + src);
    }
}

__global__ void __launch_bounds__(256, 1)
attn_kernel(const int* __restrict__ adj, float* __restrict__ out) {
    extern __shared__ char smem[];
    const uint32_t sb = smem_u32(smem);
    const int tid  = threadIdx.x;
    const int w    = tid >> 5;
    const int lane = tid & 31;
    const int wq   = w & 3;              // q band
    const int wh   = w >> 2;             // key half
    const int g    = lane >> 2;
    const int tg   = lane & 3;
    const int q0   = wq * 16;
    const int qbase = blockIdx.x * 64;

    // ---- Stage Q in slot0 (hi at 0, lo at +8192), extract A fragments.
    for (int i = 0; i < 2; i++) {
        int e = i * 256 + tid;           // 512 16B units
        int r = e >> 3, b = e & 7;
        uint32_t sw = SW128(r * 128 + b * 16);
        *(uint4*)(smem + sw) =
            *(const uint4*)(g_khhi + (qbase + r) * DD + b * 8);
        *(uint4*)(smem + 8192 + sw) =
            *(const uint4*)(g_khlo + (qbase + r) * DD + b * 8);
    }
    __syncthreads();

    uint32_t qh[16], ql[16];
    {
        int arow = q0 + ((lane >> 3) & 1) * 8 + (lane & 7);
        int acol0 = (lane >> 4) * 8;
        #pragma unroll
        for (int ks = 0; ks < 4; ks++) {
            uint32_t sw = SW128(arow * 128 + (ks * 16 + acol0) * 2);
            LDSM4(qh[4*ks], qh[4*ks+1], qh[4*ks+2], qh[4*ks+3], sb + sw);
            LDSM4(ql[4*ks], ql[4*ks+1], ql[4*ks+2], ql[4*ks+3], sb + 8192 + sw);
        }
    }
    __syncthreads();

    // Prologue fill of slot 0.
    fill_tile(sb, 0, 0, tid);
    CP_COMMIT();

    const float maxn = __uint_as_float(g_maxnorm_bits) * 0.125f * 1.0001f;
    const float mq0 = g_norm[qbase + q0 + g] * maxn;
    const float mq1 = g_norm[qbase + q0 + g + 8] * maxn;

    float o[8][4];
    #pragma unroll
    for (int i = 0; i < 8; i++)
        #pragma unroll
        for (int j = 0; j < 4; j++) o[i][j] = 0.f;
    float l0 = 0.f, l1 = 0.f;

    const int krow_l = (lane >> 4) * 8 + (lane & 7);
    const int kcol_l = ((lane >> 3) & 1) * 8;
    const int vrow_l = ((lane >> 3) & 1) * 8 + (lane & 7);
    const int vcol_l = (lane >> 4) * 8;

    for (int t = 0; t < TILES; t++) {
        const int slot = t & 1;
        const int kbase = t * 128;
        const uint32_t tbase = sb + slot * SLOT_BYTES;

        // Prefetch next tile into the other slot (its reader finished at the
        // __syncthreads that ended iteration t-1).
        if (t + 1 < TILES) { fill_tile(sb, slot ^ 1, kbase + 128, tid); CP_COMMIT(); }

        // adj ballots for this warp's 16 rows x its 64-key half (overlaps cp).
        uint2 mw0, mw1;
        #pragma unroll
        for (int rr = 0; rr < 16; rr++) {
            const int* arow = adj + (long)(qbase + q0 + rr) * NN + kbase + wh * 64;
            unsigned b0 = __ballot_sync(0xffffffffu, arow[lane] > 0);
            unsigned b1 = __ballot_sync(0xffffffffu, arow[32 + lane] > 0);
            if (rr == g)     mw0 = make_uint2(b0, b1);
            if (rr == g + 8) mw1 = make_uint2(b0, b1);
        }

        if (t + 1 < TILES) asm volatile("cp.async.wait_group 1;" ::: "memory");
        else               asm volatile("cp.async.wait_group 0;" ::: "memory");
        __syncthreads();

        // ---- S + softmax + P pack, np outer (8 f32 S live at a time)
        uint32_t ph[4][4], pl[4][4];     // [np][a-frag]
        #pragma unroll
        for (int np = 0; np < 4; np++) {
            float s0[4] = {0.f, 0.f, 0.f, 0.f};
            float s1[4] = {0.f, 0.f, 0.f, 0.f};
            #pragma unroll
            for (int ks = 0; ks < 4; ks++) {
                uint32_t sw = SW128((wh * 64 + np * 16 + krow_l) * 128 +
                                    (ks * 16 + kcol_l) * 2);
                uint32_t b0, b1, b2, b3;
                LDSM4(b0, b1, b2, b3, tbase + OFF_KHI + sw);
                mma16816(s0, qh[4*ks], qh[4*ks+1], qh[4*ks+2], qh[4*ks+3], b0, b1);
                mma16816(s1, qh[4*ks], qh[4*ks+1], qh[4*ks+2], qh[4*ks+3], b2, b3);
                mma16816(s0, ql[4*ks], ql[4*ks+1], ql[4*ks+2], ql[4*ks+3], b0, b1);
                mma16816(s1, ql[4*ks], ql[4*ks+1], ql[4*ks+2], ql[4*ks+3], b2, b3);
                uint32_t c0, c1, c2, c3;
                LDSM4(c0, c1, c2, c3, tbase + OFF_KLO + sw);
                mma16816(s0, qh[4*ks], qh[4*ks+1], qh[4*ks+2], qh[4*ks+3], c0, c1);
                mma16816(s1, qh[4*ks], qh[4*ks+1], qh[4*ks+2], qh[4*ks+3], c2, c3);
            }
            // keys: frag s0 -> 16np + {2tg, 2tg+1}; frag s1 -> +8.
            int bit = ((np & 1) << 4) + 2 * tg;
            unsigned u0 = (np < 2) ? mw0.x : mw0.y;
            unsigned u1 = (np < 2) ? mw1.x : mw1.y;
            float p00 = ((u0 >> bit) & 1u)       ? __expf(fmaf(s0[0], 0.125f, -mq0)) : 0.f;
            float p01 = ((u0 >> (bit + 1)) & 1u) ? __expf(fmaf(s0[1], 0.125f, -mq0)) : 0.f;
            float p02 = ((u1 >> bit) & 1u)       ? __expf(fmaf(s0[2], 0.125f, -mq1)) : 0.f;
            float p03 = ((u1 >> (bit + 1)) & 1u) ? __expf(fmaf(s0[3], 0.125f, -mq1)) : 0.f;
            float p10 = ((u0 >> (bit + 8)) & 1u) ? __expf(fmaf(s1[0], 0.125f, -mq0)) : 0.f;
            float p11 = ((u0 >> (bit + 9)) & 1u) ? __expf(fmaf(s1[1], 0.125f, -mq0)) : 0.f;
            float p12 = ((u1 >> (bit + 8)) & 1u) ? __expf(fmaf(s1[2], 0.125f, -mq1)) : 0.f;
            float p13 = ((u1 >> (bit + 9)) & 1u) ? __expf(fmaf(s1[3], 0.125f, -mq1)) : 0.f;
            l0 += p00 + p01 + p10 + p11;
            l1 += p02 + p03 + p12 + p13;
            __nv_bfloat16 h;
            float r;
            __nv_bfloat162 hv, rv;
            // a0: (row g, k 2tg..2tg+1) = p00,p01 ; a1: row g+8 = p02,p03
            // a2: (row g, k+8)          = p10,p11 ; a3: row g+8 = p12,p13
            h = __float2bfloat16(p00); r = p00 - __bfloat162float(h);
            __nv_bfloat16 h2 = __float2bfloat16(p01); float r2 = p01 - __bfloat162float(h2);
            hv = __halves2bfloat162(h, h2); rv = __floats2bfloat162_rn(r, r2);
            ph[np][0] = *(uint32_t*)&hv; pl[np][0] = *(uint32_t*)&rv;
            h = __float2bfloat16(p02); r = p02 - __bfloat162float(h);
            h2 = __float2bfloat16(p03); r2 = p03 - __bfloat162float(h2);
            hv = __halves2bfloat162(h, h2); rv = __floats2bfloat162_rn(r, r2);
            ph[np][1] = *(uint32_t*)&hv; pl[np][1] = *(uint32_t*)&rv;
            h = __float2bfloat16(p10); r = p10 - __bfloat162float(h);
            h2 = __float2bfloat16(p11); r2 = p11 - __bfloat162float(h2);
            hv = __halves2bfloat162(h, h2); rv = __floats2bfloat162_rn(r, r2);
            ph[np][2] = *(uint32_t*)&hv; pl[np][2] = *(uint32_t*)&rv;
            h = __float2bfloat16(p12); r = p12 - __bfloat162float(h);
            h2 = __float2bfloat16(p13); r2 = p13 - __bfloat162float(h2);
            hv = __halves2bfloat162(h, h2); rv = __floats2bfloat162_rn(r, r2);
            ph[np][3] = *(uint32_t*)&hv; pl[np][3] = *(uint32_t*)&rv;
        }

        // ---- O += P V over this key half (ks = key slice = np above)
        #pragma unroll
        for (int ks = 0; ks < 4; ks++) {
            #pragma unroll
            for (int np = 0; np < 4; np++) {
                uint32_t sw = SW128((wh * 64 + ks * 16 + vrow_l) * 128 +
                                    (np * 16 + vcol_l) * 2);
                uint32_t v0, v1, v2, v3;
                LDSM4T(v0, v1, v2, v3, tbase + OFF_VHI + sw);
                mma16816(o[2*np],   ph[ks][0], ph[ks][1], ph[ks][2], ph[ks][3], v0, v1);
                mma16816(o[2*np+1], ph[ks][0], ph[ks][1], ph[ks][2], ph[ks][3], v2, v3);
                mma16816(o[2*np],   pl[ks][0], pl[ks][1], pl[ks][2], pl[ks][3], v0, v1);
                mma16816(o[2*np+1], pl[ks][0], pl[ks][1], pl[ks][2], pl[ks][3], v2, v3);
                uint32_t u0, u1, u2, u3;
                LDSM4T(u0, u1, u2, u3, tbase + OFF_VLO + sw);
                mma16816(o[2*np],   ph[ks][0], ph[ks][1], ph[ks][2], ph[ks][3], u0, u1);
                mma16816(o[2*np+1], ph[ks][0], ph[ks][1], ph[ks][2], ph[ks][3], u2, u3);
            }
        }
        __syncthreads();   // everyone done with this slot before it refills
    }

    // ---- combine key halves: warps 4-7 dump partials, warps 0-3 finalize.
    float* cmb = (float*)smem;   // 128 threads x 34 floats = 17KB (slot0 free)
    if (wh == 1) {
        float* dst = cmb + (wq * 32 + lane) * 34;
        #pragma unroll
        for (int i = 0; i < 8; i++)
            #pragma unroll
            for (int j = 0; j < 4; j++) dst[i * 4 + j] = o[i][j];
        dst[32] = l0;
        dst[33] = l1;
    }
    __syncthreads();
    if (wh == 0) {
        const float* src = cmb + (wq * 32 + lane) * 34;
        #pragma unroll
        for (int i = 0; i < 8; i++)
            #pragma unroll
            for (int j = 0; j < 4; j++) o[i][j] += src[i * 4 + j];
        l0 += src[32];
        l1 += src[33];

        l0 += __shfl_xor_sync(0xffffffffu, l0, 1);
        l0 += __shfl_xor_sync(0xffffffffu, l0, 2);
        l1 += __shfl_xor_sync(0xffffffffu, l1, 1);
        l1 += __shfl_xor_sync(0xffffffffu, l1, 2);
        float inv0 = 1.f / l0, inv1 = 1.f / l1;

        int gr0 = qbase + q0 + g, gr1 = gr0 + 8;
        #pragma unroll
        for (int nt = 0; nt < 8; nt++) {
            float x0 = o[nt][0] * inv0; x0 = (x0 > 0.f) ? x0 : expm1f(x0);
            float x1 = o[nt][1] * inv0; x1 = (x1 > 0.f) ? x1 : expm1f(x1);
            float x2 = o[nt][2] * inv1; x2 = (x2 > 0.f) ? x2 : expm1f(x2);
            float x3 = o[nt][3] * inv1; x3 = (x3 > 0.f) ? x3 : expm1f(x3);
            *(float2*)(out + (long)gr0 * DD + nt * 8 + 2 * tg) = make_float2(x0, x1);
            *(float2*)(out + (long)gr1 * DD + nt * 8 + 2 * tg) = make_float2(x2, x3);
        }
    }
}

namespace {
struct AttrInit {
    AttrInit() {
        cudaFuncSetAttribute(attn_kernel,
                             cudaFuncAttributeMaxDynamicSharedMemorySize,
                             SMEM_ATTN);
    }
} attr_init_;
}

extern "C" void kernel_launch(void* const* d_in, const int* in_sizes, int n_in,
                              void* d_out, int out_size) {
    const float* inp = nullptr;
    const int*   adj = nullptr;
    const float* kW  = nullptr;
    const float* vW  = nullptr;
    for (int i = 0; i < n_in; i++) {
        long sz = in_sizes[i];
        if (sz == (long)NN * DIN)      inp = (const float*)d_in[i];
        else if (sz == (long)NN * NN)  adj = (const int*)d_in[i];
        else if (sz == (long)DIN * DD) { if (!kW) kW = (const float*)d_in[i];
                                         else     vW = (const float*)d_in[i]; }
    }
    float* out = (float*)d_out;

    cudaFuncSetAttribute(attn_kernel,
                         cudaFuncAttributeMaxDynamicSharedMemorySize, SMEM_ATTN);

    init_kernel<<<1, 1>>>();
    proj_kernel<<<NN / 64, dim3(16, 16)>>>(inp, kW, vW);
    norm_kernel<<<NN / 256, 256>>>();
    attn_kernel<<<NN / 64, 256, SMEM_ATTN>>>(adj, out);
}